// round 6
// baseline (speedup 1.0000x reference)
#include <cuda_runtime.h>

// PCEN stack, round 5: round-3/4 design; constexpr power helpers are now
// __host__ __device__ and all powers hoisted into named constexpr floats
// (previous rounds failed on constexpr-eval underflow / host-constexpr-in-
// device-code; no functional change to the algorithm).
//
// One block per row (8192 rows, T=2048), 128 threads x 16 elems.
// Chunked-scan filtfilt; 4 smoother chains packed 2-per-64b-register with
// fma.rn.f32x2; warp scans use shfl.sync's validity predicate to gate one
// packed FMA per step; fast pair (q^16 = 0.185/0.010) truncated to 3 steps.
//
// Epilogue identities:
//   log(EPS)+log1p(M/EPS) = log(M+EPS)
//   M'/delta = exp2(-alpha*lg2(M+EPS) - ld*log2e)
//   (x*M+d)^r - d^r = d^r*(exp2(r*lg2(1 + x*M'/d)) - 1)

typedef unsigned long long ull;

static __device__ __forceinline__ ull pk2(float x, float y) {
    ull r; asm("mov.b64 %0, {%1, %2};" : "=l"(r) : "f"(x), "f"(y)); return r;
}
static __device__ __forceinline__ void upk2(ull v, float& x, float& y) {
    asm("mov.b64 {%0, %1}, %2;" : "=f"(x), "=f"(y) : "l"(v));
}
static __device__ __forceinline__ ull fma2_(ull a, ull b, ull c) {
    ull d; asm("fma.rn.f32x2 %0, %1, %2, %3;" : "=l"(d) : "l"(a), "l"(b), "l"(c)); return d;
}
static __device__ __forceinline__ ull mul2_(ull a, ull b) {
    ull d; asm("mul.rn.f32x2 %0, %1, %2;" : "=l"(d) : "l"(a), "l"(b)); return d;
}
static __device__ __forceinline__ float ex2_(float v) {
    float r; asm("ex2.approx.f32 %0, %1;" : "=f"(r) : "f"(v)); return r;
}
static __device__ __forceinline__ float lg2_(float v) {
    float r; asm("lg2.approx.f32 %0, %1;" : "=f"(r) : "f"(v)); return r;
}

// Inclusive scan step (ascending): S += Qp * S[lane-OFF], gated by shfl predicate.
template <int OFF>
static __device__ __forceinline__ void scan_up(ull& S, ull Qp) {
    asm("{\n\t"
        ".reg .pred p;\n\t"
        ".reg .b32 sl, sh, vl, vh;\n\t"
        ".reg .b64 vv;\n\t"
        "mov.b64 {sl, sh}, %0;\n\t"
        "shfl.sync.up.b32 vl|p, sl, %2, 0, 0xffffffff;\n\t"
        "shfl.sync.up.b32 vh,   sh, %2, 0, 0xffffffff;\n\t"
        "mov.b64 vv, {vl, vh};\n\t"
        "@p fma.rn.f32x2 %0, %1, vv, %0;\n\t"
        "}" : "+l"(S) : "l"(Qp), "n"(OFF));
}
// Descending scan step: S += Qp * S[lane+OFF].
template <int OFF>
static __device__ __forceinline__ void scan_dn(ull& S, ull Qp) {
    asm("{\n\t"
        ".reg .pred p;\n\t"
        ".reg .b32 sl, sh, vl, vh;\n\t"
        ".reg .b64 vv;\n\t"
        "mov.b64 {sl, sh}, %0;\n\t"
        "shfl.sync.down.b32 vl|p, sl, %2, 0x1f, 0xffffffff;\n\t"
        "shfl.sync.down.b32 vh,   sh, %2, 0x1f, 0xffffffff;\n\t"
        "mov.b64 vv, {vl, vh};\n\t"
        "@p fma.rn.f32x2 %0, %1, vv, %0;\n\t"
        "}" : "+l"(S) : "l"(Qp), "n"(OFF));
}
// S[lane-1], zero for lane 0.
static __device__ __forceinline__ ull shup1_or_zero(ull S) {
    ull r;
    asm("{\n\t"
        ".reg .pred p;\n\t"
        ".reg .b32 sl, sh, vl, vh;\n\t"
        "mov.b64 {sl, sh}, %1;\n\t"
        "shfl.sync.up.b32 vl|p, sl, 1, 0, 0xffffffff;\n\t"
        "shfl.sync.up.b32 vh,   sh, 1, 0, 0xffffffff;\n\t"
        "mov.b64 %0, {vl, vh};\n\t"
        "@!p mov.b64 %0, 0;\n\t"
        "}" : "=l"(r) : "l"(S));
    return r;
}
// S[lane+1], zero for lane 31.
static __device__ __forceinline__ ull shdn1_or_zero(ull S) {
    ull r;
    asm("{\n\t"
        ".reg .pred p;\n\t"
        ".reg .b32 sl, sh, vl, vh;\n\t"
        "mov.b64 {sl, sh}, %1;\n\t"
        "shfl.sync.down.b32 vl|p, sl, 1, 0x1f, 0xffffffff;\n\t"
        "shfl.sync.down.b32 vh,   sh, 1, 0x1f, 0xffffffff;\n\t"
        "mov.b64 %0, {vl, vh};\n\t"
        "@!p mov.b64 %0, 0;\n\t"
        "}" : "=l"(r) : "l"(S));
    return r;
}

// Compile-time power in DOUBLE (float constexpr eval underflows at q^512);
// flush-to-zero on the float conversion. __host__ __device__ so uses inside
// device code compile without --expt-relaxed-constexpr.
static constexpr __host__ __device__ double dpow(double b, int n) {
    double r = 1.0;
    for (int i = 0; i < n; ++i) r *= b;
    return r;
}
static constexpr __host__ __device__ float cpf(double v) {
    return (v < 1.0e-37 && v > -1.0e-37) ? 0.0f : (float)v;
}

// ---- all compile-time constants hoisted to namespace scope ----
static constexpr float s0 = 0.015f, s1 = 0.04f, s2 = 0.1f, s3 = 0.25f;
static constexpr float q0 = 1.f - s0, q1 = 1.f - s1, q2 = 1.f - s2, q3 = 1.f - s3;
static constexpr float P16_0  = cpf(dpow(q0, 16)),  P16_1  = cpf(dpow(q1, 16)),
                       P16_2  = cpf(dpow(q2, 16)),  P16_3  = cpf(dpow(q3, 16));
static constexpr float P32_0  = cpf(dpow(q0, 32)),  P32_1  = cpf(dpow(q1, 32)),
                       P32_2  = cpf(dpow(q2, 32)),  P32_3  = cpf(dpow(q3, 32));
static constexpr float P64_0  = cpf(dpow(q0, 64)),  P64_1  = cpf(dpow(q1, 64)),
                       P64_2  = cpf(dpow(q2, 64)),  P64_3  = cpf(dpow(q3, 64));
static constexpr float P128_0 = cpf(dpow(q0, 128)), P128_1 = cpf(dpow(q1, 128));
static constexpr float P256_0 = cpf(dpow(q0, 256)), P256_1 = cpf(dpow(q1, 256));
static constexpr float P512_0 = cpf(dpow(q0, 512)), P512_1 = cpf(dpow(q1, 512)),
                       P512_2 = cpf(dpow(q2, 512)), P512_3 = cpf(dpow(q3, 512));

__global__ __launch_bounds__(128, 4)
void pcen_kernel(const float* __restrict__ x,
                 const float* __restrict__ i_sig_alpha,
                 const float* __restrict__ log_delta,
                 const float* __restrict__ i_sig_r,
                 const float* __restrict__ z_ks,
                 float* __restrict__ out,
                 int P, int F)
{
    constexpr int T = 2048, CH = 16, K = 4;

    const int row  = blockIdx.x;                 // ((b*P)+p)*F + f
    const int p    = (row / F) % P;
    const int f    = row % F;
    const int base = row * T;
    const int tid  = threadIdx.x;
    const int lane = tid & 31;
    const int w    = tid >> 5;

    // ---- packed per-pair constants (all halves compile-time) ----
    const ull q01c    = pk2(q0, q1);
    const ull q23c    = pk2(q2, q3);
    const ull Q512_01 = pk2(P512_0, P512_1);
    const ull Q512_23 = pk2(P512_2, P512_3);

    // per-lane geometric factors Q16^lane / Q16^(31-lane) via one ex2 each
    const float lf = (float)lane, lb = (float)(31 - lane);
    const float g0 = lg2_(P16_0), g1 = lg2_(P16_1), g2 = lg2_(P16_2), g3 = lg2_(P16_3);
    const ull Qlf01 = pk2(ex2_(lf * g0), ex2_(lf * g1));
    const ull Qlf23 = pk2(ex2_(lf * g2), ex2_(lf * g3));
    const ull Qlb01 = pk2(ex2_(lb * g0), ex2_(lb * g1));
    const ull Qlb23 = pk2(ex2_(lb * g2), ex2_(lb * g3));

    // ---- per-(p,f) scalars ----
    const float alpha  = 1.0f / (1.0f + __expf(-i_sig_alpha[p]));
    const float rr     = 1.0f / (1.0f + __expf(-i_sig_r[p]));
    const float ld     = log_delta[p];
    const float nalpha = -alpha;
    const float c2     = -ld * 1.4426950408889634f;            // -ld*log2e
    const float dr     = ex2_(rr * ld * 1.4426950408889634f);  // delta^r

    float zk0 = z_ks[(p * K + 0) * F + f];
    float zk1 = z_ks[(p * K + 1) * F + f];
    float zk2 = z_ks[(p * K + 2) * F + f];
    float zk3 = z_ks[(p * K + 3) * F + f];
    float zm = fmaxf(fmaxf(zk0, zk1), fmaxf(zk2, zk3));
    float e0 = __expf(zk0 - zm), e1 = __expf(zk1 - zm),
          e2 = __expf(zk2 - zm), e3 = __expf(zk3 - zm);
    const float inv_sum = 1.0f / (e0 + e1 + e2 + e3);
    // w_k * s_k^2 (converts scaled zt back to true units inside the mix)
    const ull ws01 = pk2(e0 * inv_sum * s0 * s0, e1 * inv_sum * s1 * s1);
    const ull ws23 = pk2(e2 * inv_sum * s2 * s2, e3 * inv_sum * s3 * s3);

    // ---- load x: 16 contiguous floats (4x LDG.128) ----
    float xr[CH];
    const float4* xv = reinterpret_cast<const float4*>(x + base + tid * CH);
#pragma unroll
    for (int j = 0; j < CH / 4; ++j) {
        float4 v = xv[j];
        xr[4*j+0] = v.x; xr[4*j+1] = v.y; xr[4*j+2] = v.z; xr[4*j+3] = v.w;
    }

    __shared__ ull  smA[4][2];
    __shared__ ull  smB[4][2];
    __shared__ ull  smInitP[2];
    __shared__ float smX0;

    // ==================== FORWARD pass ====================
    // pass1: zero-init scaled chains, packed (k0,k1) / (k2,k3)
    ull S01 = 0ull, S23 = 0ull;
#pragma unroll
    for (int i = 0; i < CH; ++i) {
        ull xx = pk2(xr[i], xr[i]);
        S01 = fma2_(q01c, S01, xx);
        S23 = fma2_(q23c, S23, xx);
    }
    S01 = mul2_(S01, pk2(s0, s1));   // true-units chunk ends
    S23 = mul2_(S23, pk2(s2, s3));

    // warp inclusive scan (pair01 full 5 steps; pair23 truncated to 3)
    scan_up<1>(S01, pk2(P16_0, P16_1));
    scan_up<2>(S01, pk2(P32_0, P32_1));
    scan_up<4>(S01, pk2(P64_0, P64_1));
    scan_up<8>(S01, pk2(P128_0, P128_1));
    scan_up<16>(S01, pk2(P256_0, P256_1));
    scan_up<1>(S23, pk2(P16_2, P16_3));
    scan_up<2>(S23, pk2(P32_2, P32_3));
    scan_up<4>(S23, pk2(P64_2, P64_3));

    if (lane == 31) { smA[w][0] = S01; smA[w][1] = S23; }
    if (tid == 0)   smX0 = xr[0];
    __syncthreads();

    // carry into this chunk
    ull sx01 = shup1_or_zero(S01);
    ull sx23 = shup1_or_zero(S23);
    const float x0s = smX0;
    ull H01 = pk2(x0s, x0s), H23 = H01;
    if (0 < w) { H01 = fma2_(Q512_01, H01, smA[0][0]); H23 = fma2_(Q512_23, H23, smA[0][1]); }
    if (1 < w) { H01 = fma2_(Q512_01, H01, smA[1][0]); H23 = fma2_(Q512_23, H23, smA[1][1]); }
    if (2 < w) { H01 = fma2_(Q512_01, H01, smA[2][0]); H23 = fma2_(Q512_23, H23, smA[2][1]); }
    ull carry01 = fma2_(Qlf01, H01, sx01);
    ull carry23 = fma2_(Qlf23, H23, sx23);

    // pass2: exact chain, keep scaled forward signal y~ = y/s
    ull yf01[CH], yf23[CH];
    {
        ull yt01 = mul2_(carry01, pk2(1.f / s0, 1.f / s1));
        ull yt23 = mul2_(carry23, pk2(1.f / s2, 1.f / s3));
#pragma unroll
        for (int i = 0; i < CH; ++i) {
            ull xx = pk2(xr[i], xr[i]);
            yt01 = fma2_(q01c, yt01, xx); yf01[i] = yt01;
            yt23 = fma2_(q23c, yt23, xx); yf23[i] = yt23;
        }
    }

    // ==================== BACKWARD pass ====================
    ull Sb01 = 0ull, Sb23 = 0ull;
#pragma unroll
    for (int i = CH - 1; i >= 0; --i) {
        Sb01 = fma2_(q01c, Sb01, yf01[i]);
        Sb23 = fma2_(q23c, Sb23, yf23[i]);
    }
    Sb01 = mul2_(Sb01, pk2(s0 * s0, s1 * s1));
    Sb23 = mul2_(Sb23, pk2(s2 * s2, s3 * s3));

    scan_dn<1>(Sb01, pk2(P16_0, P16_1));
    scan_dn<2>(Sb01, pk2(P32_0, P32_1));
    scan_dn<4>(Sb01, pk2(P64_0, P64_1));
    scan_dn<8>(Sb01, pk2(P128_0, P128_1));
    scan_dn<16>(Sb01, pk2(P256_0, P256_1));
    scan_dn<1>(Sb23, pk2(P16_2, P16_3));
    scan_dn<2>(Sb23, pk2(P32_2, P32_3));
    scan_dn<4>(Sb23, pk2(P64_2, P64_3));

    if (lane == 0) { smB[w][0] = Sb01; smB[w][1] = Sb23; }
    if (tid == 127) {
        smInitP[0] = mul2_(yf01[CH - 1], pk2(s0, s1));   // y_fwd[T-1], true units
        smInitP[1] = mul2_(yf23[CH - 1], pk2(s2, s3));
    }
    __syncthreads();

    ull sxb01 = shdn1_or_zero(Sb01);
    ull sxb23 = shdn1_or_zero(Sb23);
    ull Hb01 = smInitP[0], Hb23 = smInitP[1];
    if (3 > w) { Hb01 = fma2_(Q512_01, Hb01, smB[3][0]); Hb23 = fma2_(Q512_23, Hb23, smB[3][1]); }
    if (2 > w) { Hb01 = fma2_(Q512_01, Hb01, smB[2][0]); Hb23 = fma2_(Q512_23, Hb23, smB[2][1]); }
    if (1 > w) { Hb01 = fma2_(Q512_01, Hb01, smB[1][0]); Hb23 = fma2_(Q512_23, Hb23, smB[1][1]); }
    ull carB01 = fma2_(Qlb01, Hb01, sxb01);
    ull carB23 = fma2_(Qlb23, Hb23, sxb23);

    // pass2 backward + fused mix + PCEN epilogue + direct float4 stores
    {
        ull zt01 = mul2_(carB01, pk2(1.f / (s0 * s0), 1.f / (s1 * s1)));
        ull zt23 = mul2_(carB23, pk2(1.f / (s2 * s2), 1.f / (s3 * s3)));
        const ull eps2 = pk2(1e-6f, 0.0f);
        float ot0 = 0.f, ot1 = 0.f, ot2 = 0.f, ot3 = 0.f;
        float* outp = out + base + tid * CH;
#pragma unroll
        for (int i = CH - 1; i >= 0; --i) {
            zt01 = fma2_(q01c, zt01, yf01[i]);
            zt23 = fma2_(q23c, zt23, yf23[i]);
            ull m = fma2_(ws01, zt01, eps2);
            m = fma2_(ws23, zt23, m);
            float ma, mb; upk2(m, ma, mb);
            float Me = ma + mb;                              // M + eps
            float Mp = ex2_(fmaf(nalpha, lg2_(Me), c2));     // (M+eps)^(-a)/delta
            float u  = fmaf(xr[i], Mp, 1.0f);
            float o  = fmaf(dr, ex2_(rr * lg2_(u)), -dr);
            switch (i & 3) {
                case 0: ot0 = o; break;
                case 1: ot1 = o; break;
                case 2: ot2 = o; break;
                default: ot3 = o; break;
            }
            if ((i & 3) == 0)
                *reinterpret_cast<float4*>(outp + i) = make_float4(ot0, ot1, ot2, ot3);
        }
    }
}

extern "C" void kernel_launch(void* const* d_in, const int* in_sizes, int n_in,
                              void* d_out, int out_size)
{
    const float* x   = (const float*)d_in[0];
    const float* isa = (const float*)d_in[1];
    const float* ldl = (const float*)d_in[2];
    const float* isr = (const float*)d_in[3];
    const float* zks = (const float*)d_in[4];
    float* out = (float*)d_out;

    const int P    = in_sizes[1];                 // 4
    const int F    = in_sizes[4] / (P * 4);       // 128 (z_ks is [P,K,F], K=4)
    const int rows = in_sizes[0] / 2048;          // B*P*F = 8192

    pcen_kernel<<<rows, 128>>>(x, isa, ldl, isr, zks, out, P, F);
}